// round 14
// baseline (speedup 1.0000x reference)
#include <cuda_runtime.h>
#include <cstdint>

#define DEPTH    3
#define MARGIN   0.1f
#define BETA     0.5f
#define MAXN     16384          // max tokens (B*T); actual 2048
#define MAXWIDTH 262144         // max 2*V; actual 64000
#define TPB      128            // 4 warps/block -> all 2048 blocks co-resident (1 wave)
#define FTPB     512
#define KREG     4              // register-resident tokens/thread (covers N <= 2048)

// ---- device scratch (allocation-free; zero-initialized at module load;
//      g_hist restored to zero by final_kernel every invocation) ----
// The count-min sketch is algebraically degenerate: salts are a common
// shift per depth, so min over depths == multiplicity of (combined % width).
// One histogram row suffices; salts never reach device code.
__device__ int    g_hist[MAXWIDTH];
__device__ float4 g_row [MAXN];   // {nll, mask, rerr, pad} per row — one STG.128

// fast softplus for the bulk sum (MUFU EX2/LG2 path)
__device__ __forceinline__ float softplus_fast(float x) {
    float e = __expf(-fabsf(x));
    return fmaxf(x, 0.0f) + __logf(1.0f + e);
}
// precise softplus for the two per-row scalars feeding log()
__device__ __forceinline__ float softplus_precise(float x) {
    float e = expf(-fabsf(x));
    return fmaxf(x, 0.0f) + log1pf(e);
}
// fast tanh for x >= 0: 1 - 2/(e^{2x}+1)   (one MUFU exp + one rcp)
__device__ __forceinline__ float tanh_pos(float x) {
    return 1.0f - 2.0f * __frcp_rn(__expf(2.0f * x) + 1.0f);
}

// PDL controls
__device__ __forceinline__ void pdl_trigger() {
#if __CUDA_ARCH__ >= 900
    asm volatile("griddepcontrol.launch_dependents;");
#endif
}
__device__ __forceinline__ void pdl_wait() {
#if __CUDA_ARCH__ >= 900
    asm volatile("griddepcontrol.wait;");
#endif
}

__device__ __forceinline__ int token_bucket(const long long* inputs,
                                            const long long* targets,
                                            int n, long long width) {
    long long combined = inputs[n] * 31337LL + targets[n] * 2654435769LL;
    long long c = combined % width;
    if (c < 0) c += width;
    return (int)c;
}

// ---------------- kernel 1: pure streaming, one block per row ------------
// The only pass over the big tensor; single resident wave; unroll 8 for
// deeper per-thread MLP on the DRAM path. No elections/fences (R4/R8/R9:
// per-block gpu-scope sync costs ~20us on the stream).
__global__ void __launch_bounds__(TPB) row_kernel(const float* __restrict__ logits,
                                                  const long long* __restrict__ targets,
                                                  int V, int vec_ok) {
    pdl_trigger();

    const int r   = blockIdx.x;
    const int tid = threadIdx.x;
    const float* row = logits + (size_t)r * V;

    float acc = 0.0f;
    if (vec_ok) {
        const float4* row4 = reinterpret_cast<const float4*>(row);
        const int n4 = V >> 2;
#pragma unroll 8
        for (int i = tid; i < n4; i += TPB) {
            float4 v = __ldcs(&row4[i]);   // single-use stream: evict-first
            acc += softplus_fast(v.x);
            acc += softplus_fast(v.y);
            acc += softplus_fast(v.z);
            acc += softplus_fast(v.w);
        }
    } else {
        for (int i = tid; i < V; i += TPB)
            acc += softplus_fast(row[i]);
    }

    __shared__ float warp_sums[TPB / 32];
#pragma unroll
    for (int off = 16; off > 0; off >>= 1)
        acc += __shfl_xor_sync(0xFFFFFFFFu, acc, off);
    int lane = tid & 31, wid = tid >> 5;
    if (lane == 0) warp_sums[wid] = acc;
    __syncthreads();

    if (tid == 0) {
        float S = 0.0f;
#pragma unroll
        for (int w = 0; w < TPB / 32; w++) S += warp_sums[w];

        long long t = targets[r];
        bool valid  = (t != -1);
        int ti = (t >= 0 && t < V) ? (int)t : 0;
        float spt = softplus_precise(row[ti]);
        float spi = softplus_precise(row[0]);

        float scale = fminf(1.0f / (S + 1e-6f), 1.0f);
        float rem   = fmaxf(1.0f - S * scale, 0.0f);
        float p_t   = spt * scale + ((t == 0) ? rem : 0.0f);
        float p_i   = spi * scale + rem;

        float4 o;
        o.x = valid ? logf(fmaxf(p_t, 1e-10f)) : 0.0f;   // nll term
        o.y = valid ? 1.0f : 0.0f;                        // mask
        o.z = fmaxf(p_i - p_t + MARGIN, 0.0f);            // ranking error
        o.w = 0.0f;
        g_row[r] = o;                                     // one STG.128
    }
}

// ---------------- kernel 2: hash (overlapped) + query + reduce (PDL) -----
// Starts early via the primary's trigger; phase A (hashing) executes while
// row_kernel streams. Bucket indices for the first KREG*FTPB tokens stay in
// registers across the wait; larger N falls back to recomputation.
__global__ void __launch_bounds__(FTPB) final_kernel(const long long* __restrict__ targets,
                                                     const long long* __restrict__ inputs,
                                                     float* __restrict__ out,
                                                     int N, int V) {
    const int tid = threadIdx.x;
    const long long width = 2LL * V;

    // ---- phase A: token hashing + histogram build (overlapped) ----
    int cm[KREG];
#pragma unroll
    for (int k = 0; k < KREG; k++) {
        int n = k * FTPB + tid;
        cm[k] = (n < N) ? token_bucket(inputs, targets, n, width) : 0;
        if (n < N) atomicAdd(&g_hist[cm[k]], 1);
    }
    for (int n = KREG * FTPB + tid; n < N; n += FTPB)       // fallback (N > 2048)
        atomicAdd(&g_hist[token_bucket(inputs, targets, n, width)], 1);
    __syncthreads();   // histogram complete (single block)

    // ---- wait for row_kernel's results ----
    pdl_wait();

    // ---- phase B: query + deterministic reduction ----
    float nll_sum = 0.0f, mask_sum = 0.0f, basis_sum = 0.0f;
    float rr[KREG];

#pragma unroll
    for (int k = 0; k < KREG; k++) {          // independent load wave (LDG.128)
        int n = k * FTPB + tid;
        if (n < N) {
            float4 o = g_row[n];
            nll_sum  += o.x;
            mask_sum += o.y;
            rr[k]     = o.z;
        }
    }
#pragma unroll
    for (int k = 0; k < KREG; k++) {          // dependent gather wave
        int n = k * FTPB + tid;
        if (n < N) {
            int c = __ldcg(&g_hist[cm[k]]);
            basis_sum += rr[k] * tanh_pos((float)c * 0.1f);
        }
    }
    for (int n = KREG * FTPB + tid; n < N; n += FTPB) {     // fallback (N > 2048)
        float4 o = g_row[n];
        nll_sum  += o.x;
        mask_sum += o.y;
        int c = __ldcg(&g_hist[token_bucket(inputs, targets, n, width)]);
        basis_sum += o.z * tanh_pos((float)c * 0.1f);
    }

    __syncthreads();   // all queries done before any restore store

    // restore histogram to zero: plain stores (duplicates all write 0)
#pragma unroll
    for (int k = 0; k < KREG; k++) {
        int n = k * FTPB + tid;
        if (n < N) g_hist[cm[k]] = 0;
    }
    for (int n = KREG * FTPB + tid; n < N; n += FTPB)       // fallback (N > 2048)
        g_hist[token_bucket(inputs, targets, n, width)] = 0;

    // deterministic fixed-order reduction
    __shared__ float s0[FTPB / 32], s1[FTPB / 32], s2[FTPB / 32];
#pragma unroll
    for (int off = 16; off > 0; off >>= 1) {
        nll_sum   += __shfl_xor_sync(0xFFFFFFFFu, nll_sum,   off);
        mask_sum  += __shfl_xor_sync(0xFFFFFFFFu, mask_sum,  off);
        basis_sum += __shfl_xor_sync(0xFFFFFFFFu, basis_sum, off);
    }
    int lane = tid & 31, wid = tid >> 5;
    if (lane == 0) { s0[wid] = nll_sum; s1[wid] = mask_sum; s2[wid] = basis_sum; }
    __syncthreads();
    if (tid == 0) {
        float a = 0, b = 0, c = 0;
#pragma unroll
        for (int w = 0; w < FTPB / 32; w++) { a += s0[w]; b += s1[w]; c += s2[w]; }
        out[0] = -a / fmaxf(b, 1.0f) + BETA * (c / (float)N);
    }
}

extern "C" void kernel_launch(void* const* d_in, const int* in_sizes, int n_in,
                              void* d_out, int out_size) {
    // Resolve pointers by element count (robust to metadata ordering):
    //   salts: size == DEPTH (unused — algebraically eliminated);
    //   logits: largest; targets then inputs (relative order).
    const float*     logits  = nullptr;
    const long long* tok[2]  = {nullptr, nullptr};
    int ntok_arrays = 0;
    long long logits_size = 0;
    int N = 0;

    for (int i = 0; i < n_in; i++) {
        long long sz = in_sizes[i];
        if (sz == DEPTH) {
            // salts — common per-depth shift cancels in the min
        } else if (sz > 1000000) {
            logits = (const float*)d_in[i];
            logits_size = sz;
        } else {
            if (ntok_arrays < 2) tok[ntok_arrays] = (const long long*)d_in[i];
            ntok_arrays++;
            N = (int)sz;
        }
    }
    const long long* targets = tok[0];
    const long long* inputs  = tok[1];

    int V = (N > 0) ? (int)(logits_size / N) : 0;
    float* out = (float*)d_out;

    int vec_ok = (((uintptr_t)logits & 15) == 0) && (V % 4 == 0);

    row_kernel<<<N, TPB>>>(logits, targets, V, vec_ok);

    // PDL launch: with the primary's explicit trigger, this kernel starts
    // while row_kernel streams; phase A (hashing) is hidden entirely.
    cudaLaunchAttribute attrs[1];
    attrs[0].id = cudaLaunchAttributeProgrammaticStreamSerialization;
    attrs[0].val.programmaticStreamSerializationAllowed = 1;
    cudaLaunchConfig_t cfg = {};
    cfg.gridDim  = dim3(1, 1, 1);
    cfg.blockDim = dim3(FTPB, 1, 1);
    cfg.dynamicSmemBytes = 0;
    cfg.stream = 0;
    cfg.attrs = attrs;
    cfg.numAttrs = 1;
    cudaLaunchKernelEx(&cfg, final_kernel, targets, inputs, out, N, V);
}

// round 15
// speedup vs baseline: 1.0013x; 1.0013x over previous
#include <cuda_runtime.h>
#include <cstdint>

#define DEPTH    3
#define MARGIN   0.1f
#define BETA     0.5f
#define MAXN     16384          // max tokens (B*T); actual 2048
#define MAXWIDTH 262144         // max 2*V; actual 64000
#define TPB      128            // 4 warps/block -> all 2048 blocks co-resident (1 wave)
#define FTPB     1024
#define KREG     4              // register-resident tokens/thread (covers N <= 4096)

// ---- device scratch (allocation-free; zero-initialized at module load;
//      g_hist restored to zero by final_kernel every invocation) ----
// The count-min sketch is algebraically degenerate: salts are a common
// shift per depth, so min over depths == multiplicity of (combined % width).
__device__ int    g_hist[MAXWIDTH];
__device__ float4 g_row [MAXN];   // {nll, mask, rerr, pad} per row

// Polynomial softplus: max(x,0) + P(2e^{-|x|}-1), ONE MUFU (EX2) per element.
// P = degree-5 Chebyshev expansion of ln((3+s)/2) on s in [-1,1]
// (closed form via a = 3-2*sqrt(2)); |err| <= ~1e-5 absolute.
__device__ __forceinline__ float softplus_poly(float x) {
    float t = __expf(-fabsf(x));               // (0,1]
    float s = fmaf(2.0f, t, -1.0f);            // [-1,1]
    float p = fmaf(s, 0.000951584f, -0.003466224f);
    p = fmaf(p, s,  0.012278877f);
    p = fmaf(p, s, -0.055408280f);
    p = fmaf(p, s,  0.333341850f);
    p = fmaf(p, s,  0.405456900f);             // = log1p(t) + O(1e-5)
    return fmaxf(x, 0.0f) + p;
}
// precise softplus for the two per-row scalars feeding log()
__device__ __forceinline__ float softplus_precise(float x) {
    float e = expf(-fabsf(x));
    return fmaxf(x, 0.0f) + log1pf(e);
}
// fast tanh for x >= 0: 1 - 2/(e^{2x}+1)
__device__ __forceinline__ float tanh_pos(float x) {
    return 1.0f - 2.0f * __frcp_rn(__expf(2.0f * x) + 1.0f);
}

// PDL controls
__device__ __forceinline__ void pdl_trigger() {
#if __CUDA_ARCH__ >= 900
    asm volatile("griddepcontrol.launch_dependents;");
#endif
}
__device__ __forceinline__ void pdl_wait() {
#if __CUDA_ARCH__ >= 900
    asm volatile("griddepcontrol.wait;");
#endif
}

__device__ __forceinline__ int token_bucket(const long long* inputs,
                                            const long long* targets,
                                            int n, long long width) {
    long long combined = inputs[n] * 31337LL + targets[n] * 2654435769LL;
    long long c = combined % width;
    if (c < 0) c += width;
    return (int)c;
}

// ---------------- kernel 1: pure streaming, one block per row ------------
// The only pass over the big tensor; single resident wave; unroll 4 (R14:
// unroll 8 regressed). One MUFU per element so the stream is purely
// HBM-bound. No elections/fences (R4/R8/R9: ~20us penalty on the stream).
__global__ void __launch_bounds__(TPB) row_kernel(const float* __restrict__ logits,
                                                  const long long* __restrict__ targets,
                                                  int V, int vec_ok) {
    pdl_trigger();

    const int r   = blockIdx.x;
    const int tid = threadIdx.x;
    const float* row = logits + (size_t)r * V;

    float acc = 0.0f;
    if (vec_ok) {
        const float4* row4 = reinterpret_cast<const float4*>(row);
        const int n4 = V >> 2;
#pragma unroll 4
        for (int i = tid; i < n4; i += TPB) {
            float4 v = __ldcs(&row4[i]);   // single-use stream: evict-first
            acc += softplus_poly(v.x);
            acc += softplus_poly(v.y);
            acc += softplus_poly(v.z);
            acc += softplus_poly(v.w);
        }
    } else {
        for (int i = tid; i < V; i += TPB)
            acc += softplus_poly(row[i]);
    }

    __shared__ float warp_sums[TPB / 32];
#pragma unroll
    for (int off = 16; off > 0; off >>= 1)
        acc += __shfl_xor_sync(0xFFFFFFFFu, acc, off);
    int lane = tid & 31, wid = tid >> 5;
    if (lane == 0) warp_sums[wid] = acc;
    __syncthreads();

    if (tid == 0) {
        float S = 0.0f;
#pragma unroll
        for (int w = 0; w < TPB / 32; w++) S += warp_sums[w];

        long long t = targets[r];
        bool valid  = (t != -1);
        int ti = (t >= 0 && t < V) ? (int)t : 0;
        float spt = softplus_precise(row[ti]);
        float spi = softplus_precise(row[0]);

        float scale = fminf(1.0f / (S + 1e-6f), 1.0f);
        float rem   = fmaxf(1.0f - S * scale, 0.0f);
        float p_t   = spt * scale + ((t == 0) ? rem : 0.0f);
        float p_i   = spi * scale + rem;

        float4 o;
        o.x = valid ? logf(fmaxf(p_t, 1e-10f)) : 0.0f;   // nll term
        o.y = valid ? 1.0f : 0.0f;                        // mask
        o.z = fmaxf(p_i - p_t + MARGIN, 0.0f);            // ranking error
        o.w = 0.0f;
        g_row[r] = o;
    }
}

// ---------------- kernel 2: hash (overlapped) + query + reduce (PDL) -----
// Starts early via the primary's trigger; phase A (hashing) executes while
// row_kernel streams. Bucket indices stay in registers across the wait.
__global__ void __launch_bounds__(FTPB) final_kernel(const long long* __restrict__ targets,
                                                     const long long* __restrict__ inputs,
                                                     float* __restrict__ out,
                                                     int N, int V) {
    const int tid = threadIdx.x;
    const long long width = 2LL * V;

    // ---- phase A: token hashing + histogram build (overlapped) ----
    int cm[KREG];
#pragma unroll
    for (int k = 0; k < KREG; k++) {
        int n = k * FTPB + tid;
        cm[k] = (n < N) ? token_bucket(inputs, targets, n, width) : 0;
        if (n < N) atomicAdd(&g_hist[cm[k]], 1);
    }
    for (int n = KREG * FTPB + tid; n < N; n += FTPB)       // fallback (N > 4096)
        atomicAdd(&g_hist[token_bucket(inputs, targets, n, width)], 1);
    __syncthreads();   // histogram complete (single block)

    // ---- wait for row_kernel's results ----
    pdl_wait();

    // ---- phase B: query + deterministic reduction ----
    float nll_sum = 0.0f, mask_sum = 0.0f, basis_sum = 0.0f;
    float rr[KREG];

#pragma unroll
    for (int k = 0; k < KREG; k++) {          // independent load wave (LDG.128)
        int n = k * FTPB + tid;
        if (n < N) {
            float4 o = g_row[n];
            nll_sum  += o.x;
            mask_sum += o.y;
            rr[k]     = o.z;
        }
    }
#pragma unroll
    for (int k = 0; k < KREG; k++) {          // dependent gather wave
        int n = k * FTPB + tid;
        if (n < N) {
            int c = __ldcg(&g_hist[cm[k]]);
            basis_sum += rr[k] * tanh_pos((float)c * 0.1f);
        }
    }
    for (int n = KREG * FTPB + tid; n < N; n += FTPB) {     // fallback (N > 4096)
        float4 o = g_row[n];
        nll_sum  += o.x;
        mask_sum += o.y;
        int c = __ldcg(&g_hist[token_bucket(inputs, targets, n, width)]);
        basis_sum += o.z * tanh_pos((float)c * 0.1f);
    }

    __syncthreads();   // all queries done before any restore store

    // restore histogram to zero: plain stores (duplicates all write 0)
#pragma unroll
    for (int k = 0; k < KREG; k++) {
        int n = k * FTPB + tid;
        if (n < N) g_hist[cm[k]] = 0;
    }
    for (int n = KREG * FTPB + tid; n < N; n += FTPB)       // fallback (N > 4096)
        g_hist[token_bucket(inputs, targets, n, width)] = 0;

    // deterministic fixed-order reduction
    __shared__ float s0[FTPB / 32], s1[FTPB / 32], s2[FTPB / 32];
#pragma unroll
    for (int off = 16; off > 0; off >>= 1) {
        nll_sum   += __shfl_xor_sync(0xFFFFFFFFu, nll_sum,   off);
        mask_sum  += __shfl_xor_sync(0xFFFFFFFFu, mask_sum,  off);
        basis_sum += __shfl_xor_sync(0xFFFFFFFFu, basis_sum, off);
    }
    int lane = tid & 31, wid = tid >> 5;
    if (lane == 0) { s0[wid] = nll_sum; s1[wid] = mask_sum; s2[wid] = basis_sum; }
    __syncthreads();
    if (tid == 0) {
        float a = 0, b = 0, c = 0;
#pragma unroll
        for (int w = 0; w < FTPB / 32; w++) { a += s0[w]; b += s1[w]; c += s2[w]; }
        out[0] = -a / fmaxf(b, 1.0f) + BETA * (c / (float)N);
    }
}

extern "C" void kernel_launch(void* const* d_in, const int* in_sizes, int n_in,
                              void* d_out, int out_size) {
    // Resolve pointers by element count (robust to metadata ordering):
    //   salts: size == DEPTH (unused — algebraically eliminated);
    //   logits: largest; targets then inputs (relative order).
    const float*     logits  = nullptr;
    const long long* tok[2]  = {nullptr, nullptr};
    int ntok_arrays = 0;
    long long logits_size = 0;
    int N = 0;

    for (int i = 0; i < n_in; i++) {
        long long sz = in_sizes[i];
        if (sz == DEPTH) {
            // salts — common per-depth shift cancels in the min
        } else if (sz > 1000000) {
            logits = (const float*)d_in[i];
            logits_size = sz;
        } else {
            if (ntok_arrays < 2) tok[ntok_arrays] = (const long long*)d_in[i];
            ntok_arrays++;
            N = (int)sz;
        }
    }
    const long long* targets = tok[0];
    const long long* inputs  = tok[1];

    int V = (N > 0) ? (int)(logits_size / N) : 0;
    float* out = (float*)d_out;

    int vec_ok = (((uintptr_t)logits & 15) == 0) && (V % 4 == 0);

    row_kernel<<<N, TPB>>>(logits, targets, V, vec_ok);

    // PDL launch: with the primary's explicit trigger, this kernel starts
    // while row_kernel streams; phase A (hashing) is hidden entirely.
    cudaLaunchAttribute attrs[1];
    attrs[0].id = cudaLaunchAttributeProgrammaticStreamSerialization;
    attrs[0].val.programmaticStreamSerializationAllowed = 1;
    cudaLaunchConfig_t cfg = {};
    cfg.gridDim  = dim3(1, 1, 1);
    cfg.blockDim = dim3(FTPB, 1, 1);
    cfg.dynamicSmemBytes = 0;
    cfg.stream = 0;
    cfg.attrs = attrs;
    cfg.numAttrs = 1;
    cudaLaunchKernelEx(&cfg, final_kernel, targets, inputs, out, N, V);
}

// round 16
// speedup vs baseline: 1.0163x; 1.0150x over previous
#include <cuda_runtime.h>
#include <cstdint>

#define DEPTH    3
#define MARGIN   0.1f
#define BETA     0.5f
#define MAXN     16384          // max tokens (B*T); actual 2048
#define MAXWIDTH 262144         // max 2*V; actual 64000
#define TPB      128
#define HTPB     256
#define FTPB     256
#define FPSCALE  1073741824.0   // 2^30 fixed-point scale

// ---- device scratch (allocation-free; zero-initialized at module load;
//      g_hist/accumulators restored to zero by final_kernel every call) ----
// Count-min sketch is algebraically degenerate: salts are a common shift per
// depth, so min over depths == multiplicity of (combined % width).
__device__ int       g_hist[MAXWIDTH];
__device__ int       g_cm  [MAXN];       // bucket per token
__device__ long long g_acc_nll;          // fixed-point 2^30 accumulators
__device__ long long g_acc_mask;         // (integer adds: order-independent,
__device__ long long g_acc_basis;        //  hence bit-deterministic)

// fast softplus for the bulk sum (MUFU EX2/LG2 path)
__device__ __forceinline__ float softplus_fast(float x) {
    float e = __expf(-fabsf(x));
    return fmaxf(x, 0.0f) + __logf(1.0f + e);
}
// precise softplus for the two per-row scalars feeding log()
__device__ __forceinline__ float softplus_precise(float x) {
    float e = expf(-fabsf(x));
    return fmaxf(x, 0.0f) + log1pf(e);
}
// fast tanh for x >= 0: 1 - 2/(e^{2x}+1)
__device__ __forceinline__ float tanh_pos(float x) {
    return 1.0f - 2.0f * __frcp_rn(__expf(2.0f * x) + 1.0f);
}

// PDL controls
__device__ __forceinline__ void pdl_trigger() {
#if __CUDA_ARCH__ >= 900
    asm volatile("griddepcontrol.launch_dependents;");
#endif
}
__device__ __forceinline__ void pdl_wait() {
#if __CUDA_ARCH__ >= 900
    asm volatile("griddepcontrol.wait;");
#endif
}

__device__ __forceinline__ void red_add_s64(long long* p, long long v) {
    atomicAdd(reinterpret_cast<unsigned long long*>(p),
              static_cast<unsigned long long>(v));   // return unused -> RED
}

// ---------------- kernel 1: hash + histogram (tiny, runs first) ----------
// Triggers PDL at entry so row_kernel launches immediately; its own work
// (~2us) fully overlaps row_kernel's stream startup.
__global__ void __launch_bounds__(HTPB) hash_kernel(const long long* __restrict__ inputs,
                                                    const long long* __restrict__ targets,
                                                    int N, int V) {
    pdl_trigger();
    int n = blockIdx.x * HTPB + threadIdx.x;
    if (n < N) {
        long long width = 2LL * V;
        long long combined = inputs[n] * 31337LL + targets[n] * 2654435769LL;
        long long c = combined % width;
        if (c < 0) c += width;
        g_cm[n] = (int)c;
        atomicAdd(&g_hist[(int)c], 1);
    }
}

// ---------------- kernel 2: stream + complete per-row epilogue -----------
// One block per row; the only pass over the big tensor. Thread 0 waits on
// the (long-finished) hash grid, queries the histogram, and accumulates all
// three loss terms via fire-and-forget integer REDs (deterministic).
__global__ void __launch_bounds__(TPB) row_kernel(const float* __restrict__ logits,
                                                  const long long* __restrict__ targets,
                                                  int V, int vec_ok, int N) {
    pdl_trigger();   // let final_kernel launch early

    const int r   = blockIdx.x;
    const int tid = threadIdx.x;
    const float* row = logits + (size_t)r * V;

    float acc = 0.0f;
    if (vec_ok) {
        const float4* row4 = reinterpret_cast<const float4*>(row);
        const int n4 = V >> 2;
#pragma unroll 4
        for (int i = tid; i < n4; i += TPB) {
            float4 v = __ldcs(&row4[i]);   // single-use stream: evict-first
            acc += softplus_fast(v.x);
            acc += softplus_fast(v.y);
            acc += softplus_fast(v.z);
            acc += softplus_fast(v.w);
        }
    } else {
        for (int i = tid; i < V; i += TPB)
            acc += softplus_fast(row[i]);
    }

    __shared__ float warp_sums[TPB / 32];
#pragma unroll
    for (int off = 16; off > 0; off >>= 1)
        acc += __shfl_xor_sync(0xFFFFFFFFu, acc, off);
    int lane = tid & 31, wid = tid >> 5;
    if (lane == 0) warp_sums[wid] = acc;
    __syncthreads();

    if (tid == 0) {
        float S = 0.0f;
#pragma unroll
        for (int w = 0; w < TPB / 32; w++) S += warp_sums[w];

        long long t = targets[r];
        bool valid  = (t != -1);
        int ti = (t >= 0 && t < V) ? (int)t : 0;
        float spt = softplus_precise(row[ti]);
        float spi = softplus_precise(row[0]);

        float scale = fminf(1.0f / (S + 1e-6f), 1.0f);
        float rem   = fmaxf(1.0f - S * scale, 0.0f);
        float p_t   = spt * scale + ((t == 0) ? rem : 0.0f);
        float p_i   = spi * scale + rem;

        float nll  = valid ? logf(fmaxf(p_t, 1e-10f)) : 0.0f;
        float rerr = fmaxf(p_i - p_t + MARGIN, 0.0f);

        // histogram query (hash grid finished ~40us ago; wait is a no-op)
        pdl_wait();
        int c = __ldcg(&g_hist[__ldcg(&g_cm[r])]);
        float basis = rerr * tanh_pos((float)c * 0.1f);

        // deterministic fixed-point accumulation (fire-and-forget REDs)
        red_add_s64(&g_acc_nll,   llrint((double)nll   * FPSCALE));
        red_add_s64(&g_acc_mask,  valid ? (long long)FPSCALE : 0LL);
        red_add_s64(&g_acc_basis, llrint((double)basis * FPSCALE));
    }
}

// ---------------- kernel 3: O(1) finish + state restore (PDL) ------------
__global__ void __launch_bounds__(FTPB) final_kernel(float* __restrict__ out, int N) {
    pdl_wait();   // row grid complete => all REDs at L2
    const int tid = threadIdx.x;

    if (tid == 0) {
        double a = (double)g_acc_nll   / FPSCALE;
        double b = (double)g_acc_mask  / FPSCALE;
        double c = (double)g_acc_basis / FPSCALE;
        out[0] = (float)(-a / fmax(b, 1.0) + (double)BETA * (c / (double)N));
        g_acc_nll = 0; g_acc_mask = 0; g_acc_basis = 0;
    }
    // restore histogram to zero (duplicate buckets all write 0)
    for (int n = tid; n < N; n += FTPB)
        g_hist[__ldcg(&g_cm[n])] = 0;
}

extern "C" void kernel_launch(void* const* d_in, const int* in_sizes, int n_in,
                              void* d_out, int out_size) {
    // Resolve pointers by element count (robust to metadata ordering):
    //   salts: size == DEPTH (unused — algebraically eliminated);
    //   logits: largest; targets then inputs (relative order).
    const float*     logits  = nullptr;
    const long long* tok[2]  = {nullptr, nullptr};
    int ntok_arrays = 0;
    long long logits_size = 0;
    int N = 0;

    for (int i = 0; i < n_in; i++) {
        long long sz = in_sizes[i];
        if (sz == DEPTH) {
            // salts — common per-depth shift cancels in the min
        } else if (sz > 1000000) {
            logits = (const float*)d_in[i];
            logits_size = sz;
        } else {
            if (ntok_arrays < 2) tok[ntok_arrays] = (const long long*)d_in[i];
            ntok_arrays++;
            N = (int)sz;
        }
    }
    const long long* targets = tok[0];
    const long long* inputs  = tok[1];

    int V = (N > 0) ? (int)(logits_size / N) : 0;
    float* out = (float*)d_out;

    int vec_ok = (((uintptr_t)logits & 15) == 0) && (V % 4 == 0);

    // PDL chain: hash -> row -> final. Each predecessor triggers at entry,
    // so successors launch immediately and only their data-dependent parts
    // wait (via griddepcontrol.wait).
    cudaLaunchAttribute attrs[1];
    attrs[0].id = cudaLaunchAttributeProgrammaticStreamSerialization;
    attrs[0].val.programmaticStreamSerializationAllowed = 1;

    hash_kernel<<<(N + HTPB - 1) / HTPB, HTPB>>>(inputs, targets, N, V);

    cudaLaunchConfig_t cfg_row = {};
    cfg_row.gridDim  = dim3(N, 1, 1);
    cfg_row.blockDim = dim3(TPB, 1, 1);
    cfg_row.stream = 0;
    cfg_row.attrs = attrs;
    cfg_row.numAttrs = 1;
    cudaLaunchKernelEx(&cfg_row, row_kernel, logits, targets, V, vec_ok, N);

    cudaLaunchConfig_t cfg_fin = {};
    cfg_fin.gridDim  = dim3(1, 1, 1);
    cfg_fin.blockDim = dim3(FTPB, 1, 1);
    cfg_fin.stream = 0;
    cfg_fin.attrs = attrs;
    cfg_fin.numAttrs = 1;
    cudaLaunchKernelEx(&cfg_fin, final_kernel, out, N);
}